// round 16
// baseline (speedup 1.0000x reference)
#include <cuda_runtime.h>
#include <math.h>

// Fixed problem shape
#define NROWS 32
#define NCH   2
#define LEN   131072
#define KIIR  16384            // FIR truncation; == 4*CHUNK
#define CHUNK 4096
#define THREADS 256
#define SEG   16               // CHUNK == THREADS*SEG
#define NW    (THREADS / 32)   // 8 warps
#define CPR   32               // chunks per row
#define NBLK  (NROWS * CPR)    // 1024  (single wave at 7 CTA/SM)
#define WIN_J (KIIR / (4 * THREADS)) // 16 float4 Horner steps per thread

// Padded smem index (kills 32-way bank conflicts on per-thread segments)
#define PAD(i) ((i) + ((i) >> 5))

__device__ __forceinline__ float pow2k(float a, int sq) {
    #pragma unroll
    for (int i = 0; i < sq; i++) a *= a;
    return a;
}

// Scan domain: v[t] = x0[t]^2 + x1[t]^2  (minus aK * lagged energy when the
// lag term is non-negligible). Since env = (1-a) * scan_a(0.5 * (...)), the
// constant 0.5*(1-a) is folded into ONE epilogue FMA (fenv) instead of being
// multiplied into every element in the prologue.
__global__ void __launch_bounds__(THREADS, 7) fused(const float* __restrict__ x,
                                                    const float* __restrict__ z_alpha,
                                                    const float* __restrict__ log_threshold,
                                                    const float* __restrict__ log_ratio,
                                                    const float* __restrict__ log_knee,
                                                    float* __restrict__ out) {
    __shared__ float s[CHUNK + CHUNK / 32];
    __shared__ float wsum[NW];
    __shared__ float wred[NW];
    __shared__ float s_carry;

    const int b = blockIdx.x;
    const int n = b / CPR;
    const int c = b % CPR;
    const int tid = threadIdx.x;
    const int lane = tid & 31;
    const int wid = tid >> 5;

    const float alpha = 1.f / (1.f + expf(-z_alpha[n]));
    const float fenv  = 0.5f * (1.f - alpha);  // env = fenv * scan(v)
    const float a16   = pow2k(alpha, 4);     // alpha^16   (per-segment decay)
    const float a512  = pow2k(a16, 5);       // alpha^512  (per-warp decay)
    const float a1024 = a512 * a512;         // alpha^1024 (window Horner step)
    const float aK    = pow2k(a1024, 4);     // alpha^16384
    const float l2a   = log2f(alpha);

    // Adaptive truncation: contributions weighted below 2^-30 (~1e-9) of the
    // current sample are dropped. Deterministic, block-uniform.
    const float mneed = 30.f / fmaxf(-l2a, 1e-6f);
    int jb = (int)(mneed * (1.f / 1024.f)) + 1;      // # of trailing j-blocks
    if (jb > WIN_J) jb = WIN_J;
    const int j_start = WIN_J - jb;
    const bool use_lag = (c >= 4) && (aK > 1e-10f);  // KIIR == 4*CHUNK

    const float* __restrict__ xr = x + (size_t)n * (NCH * LEN);
    const int base = c * CHUNK;

    // ---- Prologue A: v[t] = (x0^2 + x1^2) - aK*(lagged energy) into smem
    const float4* __restrict__ x4a = (const float4*)xr;
    const float4* __restrict__ x4b = (const float4*)(xr + LEN);
    #pragma unroll
    for (int k = 0; k < CHUNK / 4 / THREADS; k++) {
        const int i4 = tid + k * THREADS;
        const int i = i4 * 4;
        const int q = (base >> 2) + i4;
        const float4 xa = x4a[q];
        const float4 xb = x4b[q];
        float4 v;
        v.x = fmaf(xa.x, xa.x, xb.x * xb.x);
        v.y = fmaf(xa.y, xa.y, xb.y * xb.y);
        v.z = fmaf(xa.z, xa.z, xb.z * xb.z);
        v.w = fmaf(xa.w, xa.w, xb.w * xb.w);
        if (use_lag) {
            const int ql = q - (KIIR >> 2);
            const float4 la = x4a[ql];
            const float4 lb = x4b[ql];
            v.x = fmaf(-aK, fmaf(la.x, la.x, lb.x * lb.x), v.x);
            v.y = fmaf(-aK, fmaf(la.y, la.y, lb.y * lb.y), v.y);
            v.z = fmaf(-aK, fmaf(la.z, la.z, lb.z * lb.z), v.z);
            v.w = fmaf(-aK, fmaf(la.w, la.w, lb.w * lb.w), v.w);
        }
        s[PAD(i)]     = v.x;
        s[PAD(i + 1)] = v.y;
        s[PAD(i + 2)] = v.z;
        s[PAD(i + 3)] = v.w;
    }

    // ---- Prologue B: incoming state via truncated, vectorized reduction.
    //   G = sum_{m=0}^{K-1} a^(K-1-m) v[base-K+m]   (raw energy units)
    //   Thread t owns float4 groups m = 1024*j + 4t; Horner in j with a^1024,
    //   in-group weights a^3..a^0, final scale a^(1020-4t). Iterations with
    //   total weight < 1e-9 are skipped (j < j_start).
    float S = 0.f;
    if (c > 0) {
        const int w0 = base - KIIR;
        const float h1 = alpha;
        const float h2 = alpha * alpha;
        const float h3 = h2 * alpha;
        for (int j = j_start; j < WIN_J; j++) {
            const int p = w0 + j * (4 * THREADS) + tid * 4;
            float l = 0.f;
            if (p >= 0) {
                const float4 xa = x4a[p >> 2];
                const float4 xb = x4b[p >> 2];
                l = h3 * fmaf(xa.x, xa.x, xb.x * xb.x);
                l = fmaf(h2, fmaf(xa.y, xa.y, xb.y * xb.y), l);
                l = fmaf(h1, fmaf(xa.z, xa.z, xb.z * xb.z), l);
                l = l + fmaf(xa.w, xa.w, xb.w * xb.w);
            }
            S = fmaf(S, a1024, l);
        }
        S *= exp2f((float)(4 * THREADS - 4 - 4 * tid) * l2a);  // a^(1020-4t)
    }
    #pragma unroll
    for (int d = 16; d > 0; d >>= 1) S += __shfl_down_sync(0xffffffffu, S, d);
    if (lane == 0) wred[wid] = S;
    __syncthreads();

    // ---- Pass 1: per-thread segment total (no per-element storage)
    const int sb = PAD(tid * SEG);
    float acc = 0.f;
    #pragma unroll
    for (int j = 0; j < SEG; j++)
        acc = fmaf(alpha, acc, s[sb + j]);

    // ---- Warp scan of segment totals (decay a16)
    float v = acc;
    float pw = a16;
    #pragma unroll
    for (int d = 1; d < 32; d <<= 1) {
        const float up = __shfl_up_sync(0xffffffffu, v, d);
        if (lane >= d) v = fmaf(pw, up, v);
        pw *= pw;
    }
    if (lane == 31) wsum[wid] = v;
    __syncthreads();

    // ---- Warp 0: scan 8 warp totals (decay a512). Warp 1: finish G.
    if (wid == 0) {
        float w = (lane < NW) ? wsum[lane] : 0.f;
        float pw2 = a512;
        #pragma unroll
        for (int d = 1; d < NW; d <<= 1) {
            const float up = __shfl_up_sync(0xffffffffu, w, d);
            if (lane >= d) w = fmaf(pw2, up, w);
            pw2 *= pw2;
        }
        if (lane < NW) wsum[lane] = w;
    }
    if (wid == 1) {
        float t = (lane < NW) ? wred[lane] : 0.f;
        #pragma unroll
        for (int d = NW / 2; d > 0; d >>= 1) t += __shfl_down_sync(0xffffffffu, t, d);
        if (lane == 0) s_carry = t;   // raw-energy incoming state
    }
    __syncthreads();

    // ---- Pass 2: rescan smem in place with full carry folded in.
    //      acc0 = warp-exclusive + a^(16*lane)*Wprev + G*a^(16*tid)
    const float G = s_carry;
    const float Wprev = (wid > 0) ? wsum[wid - 1] : 0.f;
    float vex = __shfl_up_sync(0xffffffffu, v, 1);
    if (lane == 0) vex = 0.f;
    float acc2 = vex + exp2f((float)(SEG * lane) * l2a) * Wprev
                     + G * exp2f((float)(SEG * tid) * l2a);
    #pragma unroll
    for (int j = 0; j < SEG; j++) {
        acc2 = fmaf(alpha, acc2, s[sb + j]);
        s[sb + j] = acc2;                 // s now holds scan(v); env = fenv*s
    }
    __syncthreads();

    // ---- Epilogue: gain from env, multiply, coalesced float4
    const float Tl2    = (log_threshold[n] - 6.f) * 1.44269504088896f; // T/ln2
    const float ratio  = 1.f + expf(log_ratio[n]);
    const float knee   = expf(log_knee[n] - 1.f);
    const float coef   = (1.f / ratio - 1.f) / knee;
    const float kneeT  = knee * Tl2;       // fold knee*(t1 - Tl2) into one FMA

    float4* __restrict__ o4a = (float4*)(out + (size_t)n * (NCH * LEN));
    float4* __restrict__ o4b = (float4*)(out + (size_t)n * (NCH * LEN) + LEN);

    #pragma unroll
    for (int k = 0; k < CHUNK / 4 / THREADS; k++) {
        const int i4 = tid + k * THREADS;
        const int i = i4 * 4;
        const int q = (base >> 2) + i4;

        const float ev[4] = {s[PAD(i)], s[PAD(i + 1)], s[PAD(i + 2)], s[PAD(i + 3)]};
        float g[4];
        #pragma unroll
        for (int kk = 0; kk < 4; kk++) {
            const float w   = fmaf(fenv, ev[kk], 1e-5f);
            const float t1  = __log2f(w);
            const float arg = fmaf(knee, t1, -kneeT);
            const float E   = exp2f(arg);
            float lg = __log2f(1.f + E);
            if (arg > 24.f) lg = arg;     // softplus asymptote / overflow guard
            g[kk] = exp2f(coef * lg);
        }

        const float4 xa = x4a[q];         // L1/L2-hot (loaded in prologue)
        const float4 xb = x4b[q];
        float4 oa, ob;
        oa.x = g[0] * xa.x;  ob.x = g[0] * xb.x;
        oa.y = g[1] * xa.y;  ob.y = g[1] * xb.y;
        oa.z = g[2] * xa.z;  ob.z = g[2] * xb.z;
        oa.w = g[3] * xa.w;  ob.w = g[3] * xb.w;
        o4a[q] = oa;
        o4b[q] = ob;
    }
}

extern "C" void kernel_launch(void* const* d_in, const int* in_sizes, int n_in,
                              void* d_out, int out_size) {
    const float* x  = (const float*)d_in[0];
    const float* za = (const float*)d_in[1];
    const float* lt = (const float*)d_in[2];
    const float* lr = (const float*)d_in[3];
    const float* lk = (const float*)d_in[4];
    float* out = (float*)d_out;

    fused<<<NBLK, THREADS>>>(x, za, lt, lr, lk, out);
}

// round 17
// speedup vs baseline: 1.4772x; 1.4772x over previous
#include <cuda_runtime.h>
#include <math.h>

// Fixed problem shape
#define NROWS 32
#define NCH   2
#define LEN   131072
#define KIIR  16384            // FIR truncation; == 4*CHUNK
#define CHUNK 4096
#define THREADS 256
#define SEG   16               // CHUNK == THREADS*SEG
#define NW    (THREADS / 32)   // 8 warps
#define CPR   32               // chunks per row
#define NBLK  (NROWS * CPR)    // 1024  (single wave at 7 CTA/SM)
#define WIN_J (KIIR / (4 * THREADS)) // 16 float4 Horner steps per thread

// Padded smem index (kills 32-way bank conflicts on per-thread segments)
#define PAD(i) ((i) + ((i) >> 5))

__device__ __forceinline__ float pow2k(float a, int sq) {
    #pragma unroll
    for (int i = 0; i < sq; i++) a *= a;
    return a;
}

// Scan domain: v[t] = x0^2 + x1^2 (minus aK * lagged energy when needed).
// env = 0.5*(1-a) * scan_a(v); the constant is folded into ONE epilogue FMA.
__global__ void __launch_bounds__(THREADS, 7) fused(const float* __restrict__ x,
                                                    const float* __restrict__ z_alpha,
                                                    const float* __restrict__ log_threshold,
                                                    const float* __restrict__ log_ratio,
                                                    const float* __restrict__ log_knee,
                                                    float* __restrict__ out) {
    __shared__ float s[CHUNK + CHUNK / 32];
    __shared__ float wsum[NW];
    __shared__ float wred[NW];
    __shared__ float s_carry;

    const int b = blockIdx.x;
    const int n = b / CPR;
    const int c = b % CPR;
    const int tid = threadIdx.x;
    const int lane = tid & 31;
    const int wid = tid >> 5;

    const float alpha = 1.f / (1.f + expf(-z_alpha[n]));
    const float fenv  = 0.5f * (1.f - alpha);  // env = fenv * scan(v)
    const float a16   = pow2k(alpha, 4);     // alpha^16   (per-segment decay)
    const float a512  = pow2k(a16, 5);       // alpha^512  (per-warp decay)
    const float a1024 = a512 * a512;         // alpha^1024 (window Horner step)
    const float aK    = pow2k(a1024, 4);     // alpha^16384
    const float l2a   = log2f(alpha);

    // Adaptive truncation: contributions weighted below 2^-30 (~1e-9) of the
    // current sample are dropped. Deterministic, block-uniform.
    const float mneed = 30.f / fmaxf(-l2a, 1e-6f);
    int jb = (int)(mneed * (1.f / 1024.f)) + 1;      // # of trailing j-blocks
    if (jb > WIN_J) jb = WIN_J;
    const int j_start = WIN_J - jb;
    const bool use_lag = (c >= 4) && (aK > 1e-10f);  // KIIR == 4*CHUNK

    const float* __restrict__ xr = x + (size_t)n * (NCH * LEN);
    const int base = c * CHUNK;

    // ---- Prologue A: v[t] = (x0^2+x1^2) - aK*(lagged energy) into smem.
    //      Grid-stride form (NOT explicitly unrolled): front-batching the
    //      LDGs raises MLP_p1 and triggers cross-CTA L1tex-queue spread.
    const float4* __restrict__ x4a = (const float4*)xr;
    const float4* __restrict__ x4b = (const float4*)(xr + LEN);
    for (int i4 = tid; i4 < CHUNK / 4; i4 += THREADS) {
        const int i = i4 * 4;
        const int q = (base >> 2) + i4;
        const float4 xa = x4a[q];
        const float4 xb = x4b[q];
        float4 u;
        u.x = fmaf(xa.x, xa.x, xb.x * xb.x);
        u.y = fmaf(xa.y, xa.y, xb.y * xb.y);
        u.z = fmaf(xa.z, xa.z, xb.z * xb.z);
        u.w = fmaf(xa.w, xa.w, xb.w * xb.w);
        if (use_lag) {
            const int ql = q - (KIIR >> 2);
            const float4 la = x4a[ql];
            const float4 lb = x4b[ql];
            u.x = fmaf(-aK, fmaf(la.x, la.x, lb.x * lb.x), u.x);
            u.y = fmaf(-aK, fmaf(la.y, la.y, lb.y * lb.y), u.y);
            u.z = fmaf(-aK, fmaf(la.z, la.z, lb.z * lb.z), u.z);
            u.w = fmaf(-aK, fmaf(la.w, la.w, lb.w * lb.w), u.w);
        }
        s[PAD(i)]     = u.x;
        s[PAD(i + 1)] = u.y;
        s[PAD(i + 2)] = u.z;
        s[PAD(i + 3)] = u.w;
    }

    // ---- Prologue B: incoming state via truncated, vectorized reduction.
    //   G = sum_{m=0}^{K-1} a^(K-1-m) v[base-K+m]   (raw energy units)
    //   Thread t owns float4 groups m = 1024*j + 4t; Horner in j with a^1024,
    //   in-group weights a^3..a^0, final scale a^(1020-4t). Iterations with
    //   total weight < 1e-9 are skipped (j < j_start).
    float S = 0.f;
    if (c > 0) {
        const int w0 = base - KIIR;
        const float h1 = alpha;
        const float h2 = alpha * alpha;
        const float h3 = h2 * alpha;
        for (int j = j_start; j < WIN_J; j++) {
            const int p = w0 + j * (4 * THREADS) + tid * 4;
            float l = 0.f;
            if (p >= 0) {
                const float4 xa = x4a[p >> 2];
                const float4 xb = x4b[p >> 2];
                l = h3 * fmaf(xa.x, xa.x, xb.x * xb.x);
                l = fmaf(h2, fmaf(xa.y, xa.y, xb.y * xb.y), l);
                l = fmaf(h1, fmaf(xa.z, xa.z, xb.z * xb.z), l);
                l = l + fmaf(xa.w, xa.w, xb.w * xb.w);
            }
            S = fmaf(S, a1024, l);
        }
        S *= exp2f((float)(4 * THREADS - 4 - 4 * tid) * l2a);  // a^(1020-4t)
    }
    #pragma unroll
    for (int d = 16; d > 0; d >>= 1) S += __shfl_down_sync(0xffffffffu, S, d);
    if (lane == 0) wred[wid] = S;
    __syncthreads();

    // ---- Pass 1: per-thread segment total (no per-element storage)
    const int sb = PAD(tid * SEG);
    float acc = 0.f;
    #pragma unroll
    for (int j = 0; j < SEG; j++)
        acc = fmaf(alpha, acc, s[sb + j]);

    // ---- Warp scan of segment totals (decay a16)
    float v = acc;
    float pw = a16;
    #pragma unroll
    for (int d = 1; d < 32; d <<= 1) {
        const float up = __shfl_up_sync(0xffffffffu, v, d);
        if (lane >= d) v = fmaf(pw, up, v);
        pw *= pw;
    }
    if (lane == 31) wsum[wid] = v;
    __syncthreads();

    // ---- Warp 0: scan 8 warp totals (decay a512). Warp 1: finish G.
    if (wid == 0) {
        float w = (lane < NW) ? wsum[lane] : 0.f;
        float pw2 = a512;
        #pragma unroll
        for (int d = 1; d < NW; d <<= 1) {
            const float up = __shfl_up_sync(0xffffffffu, w, d);
            if (lane >= d) w = fmaf(pw2, up, w);
            pw2 *= pw2;
        }
        if (lane < NW) wsum[lane] = w;
    }
    if (wid == 1) {
        float t = (lane < NW) ? wred[lane] : 0.f;
        #pragma unroll
        for (int d = NW / 2; d > 0; d >>= 1) t += __shfl_down_sync(0xffffffffu, t, d);
        if (lane == 0) s_carry = t;   // raw-energy incoming state
    }
    __syncthreads();

    // ---- Pass 2: rescan smem in place with full carry folded in.
    //      acc0 = warp-exclusive + a^(16*lane)*Wprev + G*a^(16*tid)
    const float G = s_carry;
    const float Wprev = (wid > 0) ? wsum[wid - 1] : 0.f;
    float vex = __shfl_up_sync(0xffffffffu, v, 1);
    if (lane == 0) vex = 0.f;
    float acc2 = vex + exp2f((float)(SEG * lane) * l2a) * Wprev
                     + G * exp2f((float)(SEG * tid) * l2a);
    #pragma unroll
    for (int j = 0; j < SEG; j++) {
        acc2 = fmaf(alpha, acc2, s[sb + j]);
        s[sb + j] = acc2;                 // s now holds scan(v); env = fenv*s
    }
    __syncthreads();

    // ---- Epilogue: gain from env, multiply, coalesced float4 (grid-stride)
    const float Tl2    = (log_threshold[n] - 6.f) * 1.44269504088896f; // T/ln2
    const float ratio  = 1.f + expf(log_ratio[n]);
    const float knee   = expf(log_knee[n] - 1.f);
    const float coef   = (1.f / ratio - 1.f) / knee;
    const float kneeT  = knee * Tl2;     // fold knee*(t1 - Tl2) into one FMA

    float4* __restrict__ o4a = (float4*)(out + (size_t)n * (NCH * LEN));
    float4* __restrict__ o4b = (float4*)(out + (size_t)n * (NCH * LEN) + LEN);

    for (int i4 = tid; i4 < CHUNK / 4; i4 += THREADS) {
        const int i = i4 * 4;
        const int q = (base >> 2) + i4;

        const float ev[4] = {s[PAD(i)], s[PAD(i + 1)], s[PAD(i + 2)], s[PAD(i + 3)]};
        float g[4];
        #pragma unroll
        for (int k = 0; k < 4; k++) {
            const float w   = fmaf(fenv, ev[k], 1e-5f);
            const float t1  = __log2f(w);
            const float arg = fmaf(knee, t1, -kneeT);
            const float E   = exp2f(arg);
            float lg = __log2f(1.f + E);
            if (arg > 24.f) lg = arg;     // softplus asymptote / overflow guard
            g[k] = exp2f(coef * lg);
        }

        const float4 xa = x4a[q];         // L1/L2-hot (loaded in prologue)
        const float4 xb = x4b[q];
        float4 oa, ob;
        oa.x = g[0] * xa.x;  ob.x = g[0] * xb.x;
        oa.y = g[1] * xa.y;  ob.y = g[1] * xb.y;
        oa.z = g[2] * xa.z;  ob.z = g[2] * xb.z;
        oa.w = g[3] * xa.w;  ob.w = g[3] * xb.w;
        o4a[q] = oa;
        o4b[q] = ob;
    }
}

extern "C" void kernel_launch(void* const* d_in, const int* in_sizes, int n_in,
                              void* d_out, int out_size) {
    const float* x  = (const float*)d_in[0];
    const float* za = (const float*)d_in[1];
    const float* lt = (const float*)d_in[2];
    const float* lr = (const float*)d_in[3];
    const float* lk = (const float*)d_in[4];
    float* out = (float*)d_out;

    fused<<<NBLK, THREADS>>>(x, za, lt, lr, lk, out);
}